// round 16
// baseline (speedup 1.0000x reference)
#include <cuda_runtime.h>

// Problem constants
#define B_  16
#define N_  64
#define S_  4
#define F0_ 8
#define C_  32
#define G_  8          // CTAs per batch (channel slices)
#define XL_ 4          // channels per slice (C_/G_)

// Cross-CTA pool combine scratch
__device__ float    g_part[B_ * G_];
__device__ unsigned g_cnt[B_];        // zero-init; atomicInc wraps -> 0 each call

// Per-CTA shared workspace (~64 KB)
struct alignas(16) Smem {
    float4 U1q[N_][C_];      // layer1 projections, s=0..3 packed    (32 KB)
    float  U1e[N_][C_];      // layer1 projection, bias-kernel slot   (8 KB)
    float  h1[N_][C_];       // layer1 activations                    (8 KB)
    float  wT1[F0_][5][C_];  // layer1 kernel weights transposed [y][s][x] (s=4: b1_kern)
    float  wrs1[F0_][C_];    // layer1 root weights [y][x]
    float  w2s[C_][16];      // layer2 kernel slice [y][s*4+xl]
    float  w2br[C_][8];      // [y][0..3: b2_kern slice, 4..7: w2_root slice]
    float  U2[N_][16];       // [i][s*4+xl]
    float  U2br[N_][8];      // [i][0..3: bias-kernel slot, 4..7: root2]
    float  bs1[C_];
    float  bs2s[XL_];
    float  red[32];
};

__global__ __launch_bounds__(1024, 1)
void fused_gnn_kernel(const float* __restrict__ x,
                      const float* __restrict__ a,
                      const float* __restrict__ e,
                      const float* __restrict__ w1k, const float* __restrict__ b1k,
                      const float* __restrict__ w1r, const float* __restrict__ b1,
                      const float* __restrict__ w2k, const float* __restrict__ b2k,
                      const float* __restrict__ w2r, const float* __restrict__ b2,
                      const float* __restrict__ wd,  const float* __restrict__ bd,
                      float* __restrict__ out)
{
    extern __shared__ Smem smem[];
    Smem& s = *smem;

    const int b    = blockIdx.x >> 3;     // batch
    const int g    = blockIdx.x & 7;      // channel slice
    const int tid  = threadIdx.x;
    const int warp = tid >> 5;
    const int lane = tid & 31;

    const float* xb = x + (size_t)b * N_ * (F0_ + 1);
    const float* ab = a + (size_t)b * N_ * N_;
    const float* eb = e + (size_t)b * N_ * N_ * S_;

    const int row0 = warp*2, row1 = row0 + 1;

    // ------------------------------------------------------------------
    // Early loads (overlap with staging): adjacency pattern (a is exactly
    // 0/1 and e is pre-masked by a, so only the ballot bits are needed),
    // and this warp's two x-rows packed into one register:
    //   lanes 0..8 -> x[row0][0..8], lanes 16..24 -> x[row1][0..8]
    // ------------------------------------------------------------------
    const float avA0 = ab[(size_t)row0*N_ + lane];
    const float avA1 = ab[(size_t)row0*N_ + 32 + lane];
    const float avB0 = ab[(size_t)row1*N_ + lane];
    const float avB1 = ab[(size_t)row1*N_ + 32 + lane];

    const int rhalf = lane >> 4;
    const int cc    = lane & 15;
    float xv01 = 0.f;
    if (cc <= F0_) xv01 = xb[(row0 + rhalf)*(F0_+1) + cc];

    // Prefetch this warp's two e-rows (2 KB contiguous = 16 x 128B lines)
    // into L1 so the data-dependent loads in msg1/msg2 are L1 hits
    // (the touched e-bytes come from DRAM; ~600cyc latency hidden here).
    if (lane < 16) {
        const char* p = (const char*)(eb + (size_t)row0 * N_ * S_) + lane * 128;
        asm volatile("prefetch.global.L1 [%0];" :: "l"(p));
    }

    // ------------------------------------------------------------------
    // Stage 0: weight staging
    // ------------------------------------------------------------------
    for (int i0 = tid; i0 < S_*C_*F0_; i0 += 1024) {
        int sI = i0 / (C_*F0_); int r = i0 - sI*(C_*F0_);
        int xx = r / F0_;       int yy = r - xx*F0_;
        s.wT1[yy][sI][xx] = w1k[i0];
    }
    if (tid < C_*F0_) {
        int xx = tid / F0_, yy = tid - xx*F0_;
        s.wT1[yy][4][xx] = b1k[tid];
    }
    if (tid < F0_*C_)
        (&s.wrs1[0][0])[tid] = w1r[tid];

    // layer2 kernel slice: w2s[y][s*4+xl] = w2k[s*(C*C) + (g*4+xl)*C + y]
    if (tid < C_*16) {
        int yy = tid & 31, l = tid >> 5;      // l = s*4+xl in 0..15
        int sI = l >> 2,   xl = l & 3;
        s.w2s[yy][l] = w2k[sI*(C_*C_) + (g*XL_ + xl)*C_ + yy];
    }
    // layer2 bias-kernel + root slice
    if (tid < C_*8) {
        int yy = tid & 31, l = tid >> 5;      // l in 0..7
        float v;
        if (l < 4) v = b2k[(g*XL_ + l)*C_ + yy];           // bias-kernel slot
        else       v = w2r[yy*C_ + g*XL_ + (l - 4)];       // root weights
        s.w2br[yy][l] = v;
    }
    if (tid < XL_) s.bs2s[tid] = b2[g*XL_ + tid];
    if (tid < C_)  s.bs1[tid]  = b1[tid];

    // Nonzero masks + row masks (register-resident, reused by msg1 & msg2)
    const unsigned mA0 = __ballot_sync(0xffffffffu, avA0 != 0.f);
    const unsigned mA1 = __ballot_sync(0xffffffffu, avA1 != 0.f);
    const unsigned mB0 = __ballot_sync(0xffffffffu, avB0 != 0.f);
    const unsigned mB1 = __ballot_sync(0xffffffffu, avB1 != 0.f);
    const float m0 = __shfl_sync(0xffffffffu, xv01, F0_);
    const float m1 = __shfl_sync(0xffffffffu, xv01, 16 + F0_);
    // If a row's mask is 0, no row t has a[t,row]!=0 (a includes valid_i),
    // so its U1/U2/h1 entries are never read: whole-warp skip when both
    // rows are masked (warp-uniform condition).
    const bool rows_live = (m0 != 0.f) || (m1 != 0.f);
    __syncthreads();

    // ------------------------------------------------------------------
    // Stage 1: prep1 (full, redundant per slice-CTA). Both rows share the
    // per-y weight loads; lane = x channel. root terms stay in registers.
    // U1 stored packed: float4 (s=0..3) + scalar (bias-kernel slot).
    // ------------------------------------------------------------------
    float rt0 = 0.f, rt1 = 0.f;
    if (rows_live) {
        float u00=0.f,u01=0.f,u02=0.f,u03=0.f,u04=0.f;
        float u10=0.f,u11=0.f,u12=0.f,u13=0.f,u14=0.f;
        float bsv = s.bs1[lane];
        rt0 = bsv; rt1 = bsv;
        #pragma unroll
        for (int y = 0; y < F0_; y++) {
            float hv0 = __shfl_sync(0xffffffffu, xv01, y);
            float hv1 = __shfl_sync(0xffffffffu, xv01, 16 + y);
            float w0 = s.wT1[y][0][lane];
            float w1 = s.wT1[y][1][lane];
            float w2 = s.wT1[y][2][lane];
            float w3 = s.wT1[y][3][lane];
            float w4 = s.wT1[y][4][lane];
            float wr = s.wrs1[y][lane];
            u00 += w0*hv0; u01 += w1*hv0; u02 += w2*hv0;
            u03 += w3*hv0; u04 += w4*hv0; rt0 += wr*hv0;
            u10 += w0*hv1; u11 += w1*hv1; u12 += w2*hv1;
            u13 += w3*hv1; u14 += w4*hv1; rt1 += wr*hv1;
        }
        s.U1q[row0][lane] = make_float4(u00, u01, u02, u03);
        s.U1e[row0][lane] = u04;
        s.U1q[row1][lane] = make_float4(u10, u11, u12, u13);
        s.U1e[row1][lane] = u14;
    }
    __syncthreads();

    // ------------------------------------------------------------------
    // Stage 2: msg1 (full), dual-row interleaved with 32-bit masks:
    // each loop retires one nonzero from row0 AND one from row1
    // (warp-uniform predicates) -> two independent load/FMA chains,
    // depth = max instead of sum per half. a==1 at every visited edge.
    // Per nz: 1 LDG.128 (e) + 1 LDS.128 + 1 LDS.32 (U1) + 5 FFMA.
    // ------------------------------------------------------------------
    if (rows_live) {
        float acc0 = 0.f, acc1 = 0.f;
        const float4* erow0 = (const float4*)(eb + (size_t)row0 * N_ * S_);
        const float4* erow1 = (const float4*)(eb + (size_t)row1 * N_ * S_);
        unsigned nz0, nz1;
        // low halves (i in 0..31)
        nz0 = mA0; nz1 = mB0;
        while (nz0 | nz1) {
            if (nz0) {
                int j = __ffs(nz0) - 1; nz0 &= nz0 - 1;
                float4 ev = erow0[j];
                float4 uq = s.U1q[j][lane];
                float  ue = s.U1e[j][lane];
                acc0 += ev.x * uq.x;
                acc0 += ev.y * uq.y;
                acc0 += ev.z * uq.z;
                acc0 += ev.w * uq.w;
                acc0 += ue;
            }
            if (nz1) {
                int j = __ffs(nz1) - 1; nz1 &= nz1 - 1;
                float4 ev = erow1[j];
                float4 uq = s.U1q[j][lane];
                float  ue = s.U1e[j][lane];
                acc1 += ev.x * uq.x;
                acc1 += ev.y * uq.y;
                acc1 += ev.z * uq.z;
                acc1 += ev.w * uq.w;
                acc1 += ue;
            }
        }
        // high halves (i in 32..63)
        nz0 = mA1; nz1 = mB1;
        while (nz0 | nz1) {
            if (nz0) {
                int j = __ffs(nz0) - 1; nz0 &= nz0 - 1;
                int i = 32 + j;
                float4 ev = erow0[i];
                float4 uq = s.U1q[i][lane];
                float  ue = s.U1e[i][lane];
                acc0 += ev.x * uq.x;
                acc0 += ev.y * uq.y;
                acc0 += ev.z * uq.z;
                acc0 += ev.w * uq.w;
                acc0 += ue;
            }
            if (nz1) {
                int j = __ffs(nz1) - 1; nz1 &= nz1 - 1;
                int i = 32 + j;
                float4 ev = erow1[i];
                float4 uq = s.U1q[i][lane];
                float  ue = s.U1e[i][lane];
                acc1 += ev.x * uq.x;
                acc1 += ev.y * uq.y;
                acc1 += ev.z * uq.z;
                acc1 += ev.w * uq.w;
                acc1 += ue;
            }
        }
        s.h1[row0][lane] = fmaxf(acc0 + rt0, 0.f) * m0;
        s.h1[row1][lane] = fmaxf(acc1 + rt1, 0.f) * m1;
    }
    __syncwarp();   // h1 produced & consumed by this warp only

    // ------------------------------------------------------------------
    // Stage 3: prep2 (slice, both rows at once).
    // lanes 0-15 -> row0, 16-31 -> row1; l = lane&15 = s*4+xl.
    // Aux accumulator (lanes 0-15 store): l2 = lane&7, rowsel2 per bit 3.
    // h1 read as lane-uniform float4 LDS (2 distinct addrs -> broadcast).
    // ------------------------------------------------------------------
    if (rows_live) {
        const int l   = lane & 15;
        const int l2  = lane & 7;
        const int rowsel  = row0 + rhalf;
        const int rowsel2 = row0 + ((lane >> 3) & 1);
        float acc  = 0.f;
        float acc2 = (l2 >= 4) ? s.bs2s[l2 & 3] : 0.f;
        #pragma unroll
        for (int y0 = 0; y0 < C_; y0 += 4) {
            float4 hm = *(const float4*)&s.h1[rowsel][y0];
            float4 ha = *(const float4*)&s.h1[rowsel2][y0];
            acc  += s.w2s[y0+0][l] * hm.x;
            acc  += s.w2s[y0+1][l] * hm.y;
            acc  += s.w2s[y0+2][l] * hm.z;
            acc  += s.w2s[y0+3][l] * hm.w;
            acc2 += s.w2br[y0+0][l2] * ha.x;
            acc2 += s.w2br[y0+1][l2] * ha.y;
            acc2 += s.w2br[y0+2][l2] * ha.z;
            acc2 += s.w2br[y0+3][l2] * ha.w;
        }
        s.U2[rowsel][l] = acc;
        if (lane < 16) s.U2br[rowsel2][l2] = acc2;
    }
    __syncthreads();

    // ------------------------------------------------------------------
    // Stage 4: msg2 (slice) + fused pool partial, HALF-WARP ROW-PARALLEL:
    // lanes 0-15 own row0, lanes 16-31 own row1 (previously duplicates).
    // l = lane&15 = sidx*4 + xl. Depth = max(c0,c1) per 32-i half.
    // ------------------------------------------------------------------
    float pacc = 0.f;
    if (rows_live) {
        const int   l    = lane & 15;
        const int   sidx = (lane >> 2) & 3;
        const int   xl   = lane & 3;
        const int   row  = row0 + rhalf;
        const float m    = rhalf ? m1 : m0;
        const float wdv  = wd[g*XL_ + xl];
        unsigned nzlo = rhalf ? mB0 : mA0;
        unsigned nzhi = rhalf ? mB1 : mA1;

        float acc = 0.f, accb = 0.f;
        const float* erowf = eb + (size_t)row * N_ * S_;
        while (__any_sync(0xffffffffu, nzlo != 0u)) {
            if (nzlo) {
                int j = __ffs(nzlo) - 1; nzlo &= nzlo - 1;
                acc  += erowf[j*S_ + sidx] * s.U2[j][l];
                accb += s.U2br[j][xl];
            }
        }
        while (__any_sync(0xffffffffu, nzhi != 0u)) {
            if (nzhi) {
                int j = __ffs(nzhi) - 1; nzhi &= nzhi - 1;
                int i = 32 + j;
                acc  += erowf[i*S_ + sidx] * s.U2[i][l];
                accb += s.U2br[i][xl];
            }
        }
        // fold the 4 s-groups (sidx lives in bits 2..3; stays in the half)
        acc += __shfl_xor_sync(0xffffffffu, acc, 4);
        acc += __shfl_xor_sync(0xffffffffu, acc, 8);
        float rt  = s.U2br[row][4 + xl];
        float val = fmaxf(acc + accb + rt, 0.f) * m;
        if (l < XL_) pacc = val * wdv;   // one lane per (row, channel)
    }

    // block-reduce pool partial
    #pragma unroll
    for (int off = 16; off > 0; off >>= 1)
        pacc += __shfl_down_sync(0xffffffffu, pacc, off);
    if (lane == 0) s.red[warp] = pacc;
    __syncthreads();
    if (warp == 0) {
        float v = s.red[lane];
        #pragma unroll
        for (int off = 16; off > 0; off >>= 1)
            v += __shfl_down_sync(0xffffffffu, v, off);
        if (lane == 0) {
            g_part[b*G_ + g] = v;
            __threadfence();
            unsigned t = atomicInc(&g_cnt[b], G_ - 1u);   // wraps to 0 each call
            if (t == G_ - 1u) {
                volatile float* p = g_part + b*G_;
                float sum = bd[0];
                #pragma unroll
                for (int k = 0; k < G_; k++) sum += p[k];
                out[b] = sum;
            }
        }
    }
}

// ---------------------------------------------------------------------------
extern "C" void kernel_launch(void* const* d_in, const int* in_sizes, int n_in,
                              void* d_out, int out_size)
{
    const float* x       = (const float*)d_in[0];
    const float* a       = (const float*)d_in[1];
    const float* e       = (const float*)d_in[2];
    const float* w1_kern = (const float*)d_in[3];
    const float* b1_kern = (const float*)d_in[4];
    const float* w1_root = (const float*)d_in[5];
    const float* b1      = (const float*)d_in[6];
    const float* w2_kern = (const float*)d_in[7];
    const float* b2_kern = (const float*)d_in[8];
    const float* w2_root = (const float*)d_in[9];
    const float* b2      = (const float*)d_in[10];
    const float* w_dense = (const float*)d_in[11];
    const float* b_dense = (const float*)d_in[12];
    float* out = (float*)d_out;

    cudaFuncSetAttribute(fused_gnn_kernel,
                         cudaFuncAttributeMaxDynamicSharedMemorySize,
                         (int)sizeof(Smem));

    fused_gnn_kernel<<<B_*G_, 1024, sizeof(Smem)>>>(
        x, a, e,
        w1_kern, b1_kern, w1_root, b1,
        w2_kern, b2_kern, w2_root, b2,
        w_dense, b_dense, out);
}

// round 17
// speedup vs baseline: 1.0022x; 1.0022x over previous
#include <cuda_runtime.h>

// Problem constants
#define B_  16
#define N_  64
#define S_  4
#define F0_ 8
#define C_  32
#define G_  8          // CTAs per batch (channel slices)
#define XL_ 4          // channels per slice (C_/G_)

// Cross-CTA pool combine scratch
__device__ float    g_part[B_ * G_];
__device__ unsigned g_cnt[B_];        // zero-init; atomicInc wraps -> 0 each call

// Per-CTA shared workspace (~64 KB)
struct alignas(16) Smem {
    float4 U1q[N_][C_];      // layer1 projections, s=0..3 packed    (32 KB)
    float  U1e[N_][C_];      // layer1 projection, bias-kernel slot   (8 KB)
    float  h1[N_][C_];       // layer1 activations                    (8 KB)
    float  wT1[F0_][5][C_];  // layer1 kernel weights transposed [y][s][x] (s=4: b1_kern)
    float  wrs1[F0_][C_];    // layer1 root weights [y][x]
    float  w2s[C_][16];      // layer2 kernel slice [y][s*4+xl]
    float  w2br[C_][8];      // [y][0..3: b2_kern slice, 4..7: w2_root slice]
    float  U2[N_][16];       // [i][s*4+xl]
    float  U2br[N_][8];      // [i][0..3: bias-kernel slot, 4..7: root2]
    float  bs1[C_];
    float  bs2s[XL_];
    float  red[32];
};

__global__ __launch_bounds__(1024, 1)
void fused_gnn_kernel(const float* __restrict__ x,
                      const float* __restrict__ a,
                      const float* __restrict__ e,
                      const float* __restrict__ w1k, const float* __restrict__ b1k,
                      const float* __restrict__ w1r, const float* __restrict__ b1,
                      const float* __restrict__ w2k, const float* __restrict__ b2k,
                      const float* __restrict__ w2r, const float* __restrict__ b2,
                      const float* __restrict__ wd,  const float* __restrict__ bd,
                      float* __restrict__ out)
{
    extern __shared__ Smem smem[];
    Smem& s = *smem;

    const int b    = blockIdx.x >> 3;     // batch
    const int g    = blockIdx.x & 7;      // channel slice
    const int tid  = threadIdx.x;
    const int warp = tid >> 5;
    const int lane = tid & 31;

    const float* xb = x + (size_t)b * N_ * (F0_ + 1);
    const float* ab = a + (size_t)b * N_ * N_;
    const float* eb = e + (size_t)b * N_ * N_ * S_;

    const int row0 = warp*2, row1 = row0 + 1;

    // ------------------------------------------------------------------
    // Early loads (overlap with staging): adjacency pattern (a is exactly
    // 0/1 and e is pre-masked by a, so only the ballot bits are needed),
    // and this warp's two x-rows packed into one register:
    //   lanes 0..8 -> x[row0][0..8], lanes 16..24 -> x[row1][0..8]
    // ------------------------------------------------------------------
    const float avA0 = ab[(size_t)row0*N_ + lane];
    const float avA1 = ab[(size_t)row0*N_ + 32 + lane];
    const float avB0 = ab[(size_t)row1*N_ + lane];
    const float avB1 = ab[(size_t)row1*N_ + 32 + lane];

    const int rhalf = lane >> 4;
    const int cc    = lane & 15;
    float xv01 = 0.f;
    if (cc <= F0_) xv01 = xb[(row0 + rhalf)*(F0_+1) + cc];

    // Prefetch this warp's two e-rows (2 KB contiguous = 16 x 128B lines)
    // into L1 so the data-dependent loads in msg1/msg2 are L1 hits
    // (the touched e-bytes come from DRAM; ~600cyc latency hidden here).
    if (lane < 16) {
        const char* p = (const char*)(eb + (size_t)row0 * N_ * S_) + lane * 128;
        asm volatile("prefetch.global.L1 [%0];" :: "l"(p));
    }

    // ------------------------------------------------------------------
    // Stage 0: weight staging
    // ------------------------------------------------------------------
    for (int i0 = tid; i0 < S_*C_*F0_; i0 += 1024) {
        int sI = i0 / (C_*F0_); int r = i0 - sI*(C_*F0_);
        int xx = r / F0_;       int yy = r - xx*F0_;
        s.wT1[yy][sI][xx] = w1k[i0];
    }
    if (tid < C_*F0_) {
        int xx = tid / F0_, yy = tid - xx*F0_;
        s.wT1[yy][4][xx] = b1k[tid];
    }
    if (tid < F0_*C_)
        (&s.wrs1[0][0])[tid] = w1r[tid];

    // layer2 kernel slice: w2s[y][s*4+xl] = w2k[s*(C*C) + (g*4+xl)*C + y]
    if (tid < C_*16) {
        int yy = tid & 31, l = tid >> 5;      // l = s*4+xl in 0..15
        int sI = l >> 2,   xl = l & 3;
        s.w2s[yy][l] = w2k[sI*(C_*C_) + (g*XL_ + xl)*C_ + yy];
    }
    // layer2 bias-kernel + root slice
    if (tid < C_*8) {
        int yy = tid & 31, l = tid >> 5;      // l in 0..7
        float v;
        if (l < 4) v = b2k[(g*XL_ + l)*C_ + yy];           // bias-kernel slot
        else       v = w2r[yy*C_ + g*XL_ + (l - 4)];       // root weights
        s.w2br[yy][l] = v;
    }
    if (tid < XL_) s.bs2s[tid] = b2[g*XL_ + tid];
    if (tid < C_)  s.bs1[tid]  = b1[tid];

    // Nonzero masks + row masks (register-resident, reused by msg1 & msg2)
    const unsigned mA0 = __ballot_sync(0xffffffffu, avA0 != 0.f);
    const unsigned mA1 = __ballot_sync(0xffffffffu, avA1 != 0.f);
    const unsigned mB0 = __ballot_sync(0xffffffffu, avB0 != 0.f);
    const unsigned mB1 = __ballot_sync(0xffffffffu, avB1 != 0.f);
    const float m0 = __shfl_sync(0xffffffffu, xv01, F0_);
    const float m1 = __shfl_sync(0xffffffffu, xv01, 16 + F0_);
    // If a row's mask is 0, no row t has a[t,row]!=0 (a includes valid_i),
    // so its U1/U2/h1 entries are never read: whole-warp skip when both
    // rows are masked (warp-uniform condition).
    const bool rows_live = (m0 != 0.f) || (m1 != 0.f);
    __syncthreads();

    // ------------------------------------------------------------------
    // Stage 1: prep1 (full, redundant per slice-CTA). Both rows share the
    // per-y weight loads; lane = x channel. root terms stay in registers.
    // U1 stored packed: float4 (s=0..3) + scalar (bias-kernel slot).
    // ------------------------------------------------------------------
    float rt0 = 0.f, rt1 = 0.f;
    if (rows_live) {
        float u00=0.f,u01=0.f,u02=0.f,u03=0.f,u04=0.f;
        float u10=0.f,u11=0.f,u12=0.f,u13=0.f,u14=0.f;
        float bsv = s.bs1[lane];
        rt0 = bsv; rt1 = bsv;
        #pragma unroll
        for (int y = 0; y < F0_; y++) {
            float hv0 = __shfl_sync(0xffffffffu, xv01, y);
            float hv1 = __shfl_sync(0xffffffffu, xv01, 16 + y);
            float w0 = s.wT1[y][0][lane];
            float w1 = s.wT1[y][1][lane];
            float w2 = s.wT1[y][2][lane];
            float w3 = s.wT1[y][3][lane];
            float w4 = s.wT1[y][4][lane];
            float wr = s.wrs1[y][lane];
            u00 += w0*hv0; u01 += w1*hv0; u02 += w2*hv0;
            u03 += w3*hv0; u04 += w4*hv0; rt0 += wr*hv0;
            u10 += w0*hv1; u11 += w1*hv1; u12 += w2*hv1;
            u13 += w3*hv1; u14 += w4*hv1; rt1 += wr*hv1;
        }
        s.U1q[row0][lane] = make_float4(u00, u01, u02, u03);
        s.U1e[row0][lane] = u04;
        s.U1q[row1][lane] = make_float4(u10, u11, u12, u13);
        s.U1e[row1][lane] = u14;
    }
    __syncthreads();

    // ------------------------------------------------------------------
    // Stage 2: msg1 (full), dual-row interleaved with 32-bit masks:
    // each loop retires one nonzero from row0 AND one from row1
    // (warp-uniform predicates) -> two independent load/FMA chains,
    // depth = max instead of sum per half. a==1 at every visited edge.
    // Per nz: 1 LDG.128 (e) + 1 LDS.128 + 1 LDS.32 (U1) + 5 FFMA.
    // ------------------------------------------------------------------
    if (rows_live) {
        float acc0 = 0.f, acc1 = 0.f;
        const float4* erow0 = (const float4*)(eb + (size_t)row0 * N_ * S_);
        const float4* erow1 = (const float4*)(eb + (size_t)row1 * N_ * S_);
        unsigned nz0, nz1;
        // low halves (i in 0..31)
        nz0 = mA0; nz1 = mB0;
        while (nz0 | nz1) {
            if (nz0) {
                int j = __ffs(nz0) - 1; nz0 &= nz0 - 1;
                float4 ev = erow0[j];
                float4 uq = s.U1q[j][lane];
                float  ue = s.U1e[j][lane];
                acc0 += ev.x * uq.x;
                acc0 += ev.y * uq.y;
                acc0 += ev.z * uq.z;
                acc0 += ev.w * uq.w;
                acc0 += ue;
            }
            if (nz1) {
                int j = __ffs(nz1) - 1; nz1 &= nz1 - 1;
                float4 ev = erow1[j];
                float4 uq = s.U1q[j][lane];
                float  ue = s.U1e[j][lane];
                acc1 += ev.x * uq.x;
                acc1 += ev.y * uq.y;
                acc1 += ev.z * uq.z;
                acc1 += ev.w * uq.w;
                acc1 += ue;
            }
        }
        // high halves (i in 32..63)
        nz0 = mA1; nz1 = mB1;
        while (nz0 | nz1) {
            if (nz0) {
                int j = __ffs(nz0) - 1; nz0 &= nz0 - 1;
                int i = 32 + j;
                float4 ev = erow0[i];
                float4 uq = s.U1q[i][lane];
                float  ue = s.U1e[i][lane];
                acc0 += ev.x * uq.x;
                acc0 += ev.y * uq.y;
                acc0 += ev.z * uq.z;
                acc0 += ev.w * uq.w;
                acc0 += ue;
            }
            if (nz1) {
                int j = __ffs(nz1) - 1; nz1 &= nz1 - 1;
                int i = 32 + j;
                float4 ev = erow1[i];
                float4 uq = s.U1q[i][lane];
                float  ue = s.U1e[i][lane];
                acc1 += ev.x * uq.x;
                acc1 += ev.y * uq.y;
                acc1 += ev.z * uq.z;
                acc1 += ev.w * uq.w;
                acc1 += ue;
            }
        }
        s.h1[row0][lane] = fmaxf(acc0 + rt0, 0.f) * m0;
        s.h1[row1][lane] = fmaxf(acc1 + rt1, 0.f) * m1;
    }
    __syncwarp();   // h1 produced & consumed by this warp only

    // ------------------------------------------------------------------
    // Stage 3: prep2 (slice, both rows at once).
    // lanes 0-15 -> row0, 16-31 -> row1; l = lane&15 = s*4+xl.
    // Aux accumulator (lanes 0-15 store): l2 = lane&7, rowsel2 per bit 3.
    // h1 read as lane-uniform float4 LDS (2 distinct addrs -> broadcast).
    // ------------------------------------------------------------------
    if (rows_live) {
        const int l   = lane & 15;
        const int l2  = lane & 7;
        const int rowsel  = row0 + rhalf;
        const int rowsel2 = row0 + ((lane >> 3) & 1);
        float acc  = 0.f;
        float acc2 = (l2 >= 4) ? s.bs2s[l2 & 3] : 0.f;
        #pragma unroll
        for (int y0 = 0; y0 < C_; y0 += 4) {
            float4 hm = *(const float4*)&s.h1[rowsel][y0];
            float4 ha = *(const float4*)&s.h1[rowsel2][y0];
            acc  += s.w2s[y0+0][l] * hm.x;
            acc  += s.w2s[y0+1][l] * hm.y;
            acc  += s.w2s[y0+2][l] * hm.z;
            acc  += s.w2s[y0+3][l] * hm.w;
            acc2 += s.w2br[y0+0][l2] * ha.x;
            acc2 += s.w2br[y0+1][l2] * ha.y;
            acc2 += s.w2br[y0+2][l2] * ha.z;
            acc2 += s.w2br[y0+3][l2] * ha.w;
        }
        s.U2[rowsel][l] = acc;
        if (lane < 16) s.U2br[rowsel2][l2] = acc2;
    }
    __syncthreads();

    // ------------------------------------------------------------------
    // Stage 4: msg2 (slice) + fused pool partial, HALF-WARP ROW-PARALLEL:
    // lanes 0-15 own row0, lanes 16-31 own row1 (previously duplicates).
    // l = lane&15 = sidx*4 + xl. Depth = max(c0,c1) per 32-i half.
    // ------------------------------------------------------------------
    float pacc = 0.f;
    if (rows_live) {
        const int   l    = lane & 15;
        const int   sidx = (lane >> 2) & 3;
        const int   xl   = lane & 3;
        const int   row  = row0 + rhalf;
        const float m    = rhalf ? m1 : m0;
        const float wdv  = wd[g*XL_ + xl];
        unsigned nzlo = rhalf ? mB0 : mA0;
        unsigned nzhi = rhalf ? mB1 : mA1;

        float acc = 0.f, accb = 0.f;
        const float* erowf = eb + (size_t)row * N_ * S_;
        while (__any_sync(0xffffffffu, nzlo != 0u)) {
            if (nzlo) {
                int j = __ffs(nzlo) - 1; nzlo &= nzlo - 1;
                acc  += erowf[j*S_ + sidx] * s.U2[j][l];
                accb += s.U2br[j][xl];
            }
        }
        while (__any_sync(0xffffffffu, nzhi != 0u)) {
            if (nzhi) {
                int j = __ffs(nzhi) - 1; nzhi &= nzhi - 1;
                int i = 32 + j;
                acc  += erowf[i*S_ + sidx] * s.U2[i][l];
                accb += s.U2br[i][xl];
            }
        }
        // fold the 4 s-groups (sidx lives in bits 2..3; stays in the half)
        acc += __shfl_xor_sync(0xffffffffu, acc, 4);
        acc += __shfl_xor_sync(0xffffffffu, acc, 8);
        float rt  = s.U2br[row][4 + xl];
        float val = fmaxf(acc + accb + rt, 0.f) * m;
        if (l < XL_) pacc = val * wdv;   // one lane per (row, channel)
    }

    // block-reduce pool partial
    #pragma unroll
    for (int off = 16; off > 0; off >>= 1)
        pacc += __shfl_down_sync(0xffffffffu, pacc, off);
    if (lane == 0) s.red[warp] = pacc;
    __syncthreads();
    if (warp == 0) {
        float v = s.red[lane];
        #pragma unroll
        for (int off = 16; off > 0; off >>= 1)
            v += __shfl_down_sync(0xffffffffu, v, off);
        if (lane == 0) {
            g_part[b*G_ + g] = v;
            __threadfence();
            unsigned t = atomicInc(&g_cnt[b], G_ - 1u);   // wraps to 0 each call
            if (t == G_ - 1u) {
                volatile float* p = g_part + b*G_;
                float sum = bd[0];
                #pragma unroll
                for (int k = 0; k < G_; k++) sum += p[k];
                out[b] = sum;
            }
        }
    }
}

// ---------------------------------------------------------------------------
extern "C" void kernel_launch(void* const* d_in, const int* in_sizes, int n_in,
                              void* d_out, int out_size)
{
    const float* x       = (const float*)d_in[0];
    const float* a       = (const float*)d_in[1];
    const float* e       = (const float*)d_in[2];
    const float* w1_kern = (const float*)d_in[3];
    const float* b1_kern = (const float*)d_in[4];
    const float* w1_root = (const float*)d_in[5];
    const float* b1      = (const float*)d_in[6];
    const float* w2_kern = (const float*)d_in[7];
    const float* b2_kern = (const float*)d_in[8];
    const float* w2_root = (const float*)d_in[9];
    const float* b2      = (const float*)d_in[10];
    const float* w_dense = (const float*)d_in[11];
    const float* b_dense = (const float*)d_in[12];
    float* out = (float*)d_out;

    cudaFuncSetAttribute(fused_gnn_kernel,
                         cudaFuncAttributeMaxDynamicSharedMemorySize,
                         (int)sizeof(Smem));

    fused_gnn_kernel<<<B_*G_, 1024, sizeof(Smem)>>>(
        x, a, e,
        w1_kern, b1_kern, w1_root, b1,
        w2_kern, b2_kern, w2_root, b2,
        w_dense, b_dense, out);
}